// round 8
// baseline (speedup 1.0000x reference)
#include <cuda_runtime.h>
#include <cuda_bf16.h>
#include <stdint.h>

#define NH 16
#define Dh 64
#define Lq 1024
#define Bq 4
#define Eq 1024
#define BH 64

// ---- scratch (device globals) ----
__device__ float g_q[BH*Lq*Dh];          // (BH,L,D), q pre-scaled by 1/8
__device__ float g_k[BH*Lq*Dh];          // (BH,L,D)
__device__ float g_v[BH*Lq*Dh];          // (BH,D,L)  TRANSPOSED for PV
__device__ float g_qe[(size_t)BH*Lq*Lq]; // relpos logits (band tiles only)
__device__ float g_ctx[Lq*Bq*Eq];        // (L,B,E)

#define SWZ64(x)  ((x) ^ (((x) >> 3) & 0x30))
#define SWZ128(x) ((x) ^ (((x) >> 3) & 0x70))
#define SWZ256(x) ((x) ^ (((x) >> 4) & 0x70))

__device__ __forceinline__ void ldsm4(uint32_t (&r)[4], uint32_t addr) {
    asm volatile("ldmatrix.sync.aligned.m8n8.x4.shared.b16 {%0,%1,%2,%3}, [%4];"
                 : "=r"(r[0]), "=r"(r[1]), "=r"(r[2]), "=r"(r[3]) : "r"(addr));
}
__device__ __forceinline__ void mma_bf16(float (&d)[4], const uint32_t (&a)[4],
                                         uint32_t b0, uint32_t b1) {
    asm volatile("mma.sync.aligned.m16n8k16.row.col.f32.bf16.bf16.f32 "
                 "{%0,%1,%2,%3}, {%4,%5,%6,%7}, {%8,%9}, {%0,%1,%2,%3};"
                 : "+f"(d[0]), "+f"(d[1]), "+f"(d[2]), "+f"(d[3])
                 : "r"(a[0]), "r"(a[1]), "r"(a[2]), "r"(a[3]), "r"(b0), "r"(b1));
}
__device__ __forceinline__ void split_bf16(float4 v, uint2& hi, uint2& lo) {
    __nv_bfloat162 h0 = __floats2bfloat162_rn(v.x, v.y);
    __nv_bfloat162 h1 = __floats2bfloat162_rn(v.z, v.w);
    __nv_bfloat162 l0 = __floats2bfloat162_rn(v.x - __low2float(h0),  v.y - __high2float(h0));
    __nv_bfloat162 l1 = __floats2bfloat162_rn(v.z - __low2float(h1),  v.w - __high2float(h1));
    hi = make_uint2(*(uint32_t*)&h0, *(uint32_t*)&h1);
    lo = make_uint2(*(uint32_t*)&l0, *(uint32_t*)&l1);
}
__device__ __forceinline__ uint32_t packbf(float a, float b) {
    __nv_bfloat162 t = __floats2bfloat162_rn(a, b);
    return *(uint32_t*)&t;
}

// ---------------------------------------------------------------------------
// Double-buffered GEMM: C(128 x NT) = A(128 x K) * B(NT x K)^T
// 256 thr, warp grid 2x4. Dynamic smem: 2 stages of (A 16KB + B NT*128 B).
// One __syncthreads per 32-K iteration; LDG for next stage in flight over MMA.
// ---------------------------------------------------------------------------
template<int NT, class Epi>
__device__ __forceinline__ void mm_main(const float* __restrict__ A, int lda,
                                        const float* __restrict__ B, int ldb,
                                        int K, Epi epi)
{
    constexpr int WN   = NT / 4;
    constexpr int NTN8 = WN / 8;
    constexpr int NB16 = WN / 16;
    constexpr int BI   = NT / 32;
    constexpr int ASZ  = 8192;         // 128 x 32 bf16
    constexpr int BSZ  = NT * 64;      // NT x 32 bf16
    constexpr int STG  = 2 * ASZ + 2 * BSZ;

    extern __shared__ char dsm[];
    const uint32_t su = (uint32_t)__cvta_generic_to_shared(dsm);

    const int tid  = threadIdx.x;
    const int lane = tid & 31, w = tid >> 5;
    const int m_base = (w & 1) * 64;
    const int n_base = (w >> 1) * WN;

    float acc[4][NTN8][4];
    #pragma unroll
    for (int i = 0; i < 4; i++)
        #pragma unroll
        for (int j = 0; j < NTN8; j++)
            #pragma unroll
            for (int q = 0; q < 4; q++) acc[i][j][q] = 0.f;

    const uint32_t a_row = lane & 15;
    const uint32_t a_k8  = (lane >> 4) * 8;
    const uint32_t b_row = (lane & 7) + ((lane >> 4) & 1) * 8;
    const uint32_t b_k8  = ((lane >> 3) & 1) * 8;

    float4 va[4], vb[BI];

    auto gload = [&](int kb) {
        #pragma unroll
        for (int i = 0; i < 4; i++) {
            int qd = tid + i * 256; int r = qd >> 3, c = (qd & 7) * 4;
            va[i] = *(const float4*)(A + (size_t)r * lda + kb + c);
        }
        #pragma unroll
        for (int i = 0; i < BI; i++) {
            int qd = tid + i * 256; int r = qd >> 3, c = (qd & 7) * 4;
            vb[i] = *(const float4*)(B + (size_t)r * ldb + kb + c);
        }
    };
    auto sstore = [&](int s) {
        char* base = dsm + s * STG;
        #pragma unroll
        for (int i = 0; i < 4; i++) {
            int qd = tid + i * 256; int r = qd >> 3, c = (qd & 7) * 4;
            uint2 hi, lo; split_bf16(va[i], hi, lo);
            uint32_t off = SWZ64((uint32_t)(r * 64 + c * 2));
            *(uint2*)(base + off)       = hi;
            *(uint2*)(base + ASZ + off) = lo;
        }
        #pragma unroll
        for (int i = 0; i < BI; i++) {
            int qd = tid + i * 256; int r = qd >> 3, c = (qd & 7) * 4;
            uint2 hi, lo; split_bf16(vb[i], hi, lo);
            uint32_t off = SWZ64((uint32_t)(r * 64 + c * 2));
            *(uint2*)(base + 2 * ASZ + off)       = hi;
            *(uint2*)(base + 2 * ASZ + BSZ + off) = lo;
        }
    };
    auto domma = [&](int s) {
        const uint32_t sbA  = su + s * STG;
        const uint32_t sbAl = sbA + ASZ;
        const uint32_t sbB  = sbA + 2 * ASZ;
        const uint32_t sbBl = sbB + BSZ;
        #pragma unroll
        for (int kc = 0; kc < 2; kc++) {
            uint32_t ah[4][4], al[4][4];
            #pragma unroll
            for (int mt = 0; mt < 4; mt++) {
                uint32_t off = SWZ64((uint32_t)((m_base + mt * 16 + a_row) * 64
                                                + (kc * 16 + a_k8) * 2));
                ldsm4(ah[mt], sbA  + off);
                ldsm4(al[mt], sbAl + off);
            }
            uint32_t bh[NB16][4], bl[NB16][4];
            #pragma unroll
            for (int nb = 0; nb < NB16; nb++) {
                uint32_t off = SWZ64((uint32_t)((n_base + nb * 16 + b_row) * 64
                                                + (kc * 16 + b_k8) * 2));
                ldsm4(bh[nb], sbB  + off);
                ldsm4(bl[nb], sbBl + off);
            }
            #pragma unroll
            for (int mt = 0; mt < 4; mt++)
                #pragma unroll
                for (int nt = 0; nt < NTN8; nt++) {
                    uint32_t b0h = bh[nt >> 1][(nt & 1) * 2];
                    uint32_t b1h = bh[nt >> 1][(nt & 1) * 2 + 1];
                    uint32_t b0l = bl[nt >> 1][(nt & 1) * 2];
                    uint32_t b1l = bl[nt >> 1][(nt & 1) * 2 + 1];
                    mma_bf16(acc[mt][nt], ah[mt], b0h, b1h);
                    mma_bf16(acc[mt][nt], ah[mt], b0l, b1l);
                    mma_bf16(acc[mt][nt], al[mt], b0h, b1h);
                }
        }
    };

    gload(0); sstore(0); __syncthreads();
    const int nk = K >> 5;
    for (int i = 0; i < nk; i++) {
        if (i + 1 < nk) gload((i + 1) << 5);   // LDGs in flight over MMA
        domma(i & 1);
        if (i + 1 < nk) sstore((i + 1) & 1);
        __syncthreads();
    }

    #pragma unroll
    for (int mt = 0; mt < 4; mt++)
        #pragma unroll
        for (int nt = 0; nt < NTN8; nt++) {
            int m = m_base + mt * 16 + (lane >> 2);
            int n = n_base + nt * 8 + (lane & 3) * 2;
            epi(m,     n, make_float2(acc[mt][nt][0], acc[mt][nt][1]));
            epi(m + 8, n, make_float2(acc[mt][nt][2], acc[mt][nt][3]));
        }
}

// ---------------------------------------------------------------------------
// Epilogues
// ---------------------------------------------------------------------------
struct EpiQKV {
    int m0, n0; const float* bias;
    __device__ __forceinline__ void operator()(int mi, int ni, float2 v) const {
        int m = m0 + mi, n = n0 + ni;
        float2 bb = *(const float2*)(bias + n);
        v.x += bb.x; v.y += bb.y;
        int l = m >> 2, b = m & 3;
        int sec = n >> 10, e = n & 1023, h = e >> 6, d = e & 63;
        if (sec == 0) {
            v.x *= 0.125f; v.y *= 0.125f;
            *(float2*)(g_q + (((b * NH + h) * Lq + l) * Dh + d)) = v;
        } else if (sec == 1) {
            *(float2*)(g_k + (((b * NH + h) * Lq + l) * Dh + d)) = v;
        } else {
            size_t idx = ((size_t)(b * NH + h) * Dh + d) * Lq + l;
            g_v[idx]      = v.x;
            g_v[idx + Lq] = v.y;
        }
    }
};
struct EpiStore {
    float* C; int m0, n0;
    __device__ __forceinline__ void operator()(int mi, int ni, float2 v) const {
        *(float2*)(C + (size_t)(m0 + mi) * Lq + (n0 + ni)) = v;
    }
};
struct EpiBias {
    float* C; const float* bias; int m0, n0;
    __device__ __forceinline__ void operator()(int mi, int ni, float2 v) const {
        float2 bb = *(const float2*)(bias + n0 + ni);
        v.x += bb.x; v.y += bb.y;
        *(float2*)(C + (size_t)(m0 + mi) * Eq + (n0 + ni)) = v;
    }
};

// ---------------------------------------------------------------------------
__global__ __launch_bounds__(256, 1) void k_qkv(const float* __restrict__ q,
                                                const float* __restrict__ W,
                                                const float* __restrict__ bias) {
    EpiQKV e{(int)blockIdx.y * 128, (int)blockIdx.x * 128, bias};
    mm_main<128>(q + (size_t)e.m0 * Eq, Eq, W + (size_t)e.n0 * Eq, Eq, Eq, e);
}

__global__ __launch_bounds__(256, 1) void k_qe(const float* __restrict__ er) {
    if (blockIdx.x + blockIdx.y < 7) return;   // band tiles only
    int bh = blockIdx.z;
    int m0 = blockIdx.y * 128, n0 = blockIdx.x * 128;
    EpiStore e{g_qe + (size_t)bh * Lq * Lq, m0, n0};
    mm_main<128>(g_q + (size_t)bh * Lq * Dh + (size_t)m0 * Dh, Dh,
                 er + (size_t)n0 * Dh, Dh, Dh, e);
}

// ---------------------------------------------------------------------------
// Fused attention, double-buffered K/V stages (2 x 64KB dynamic smem)
// ---------------------------------------------------------------------------
__global__ __launch_bounds__(256, 1) void k_attn() {
    extern __shared__ char sm[];
    const uint32_t su = (uint32_t)__cvta_generic_to_shared(sm);
    // stage s: Kh = s*65536, Kl = +16384, Vh = +32768, Vl = +49152

    const int tid = threadIdx.x, lane = tid & 31, w = tid >> 5;
    const int m0 = blockIdx.x * 128, bh = blockIdx.y;
    const int rb = w * 16;

    const float* __restrict__ Qg = g_q + (size_t)bh * Lq * Dh + (size_t)m0 * Dh;
    const float* __restrict__ Kg = g_k + (size_t)bh * Lq * Dh;
    const float* __restrict__ Vg = g_v + (size_t)bh * Dh * Lq;   // (D, L)

    // ---- stage Q through stage0 K area, pull A-frags to registers ----
    #pragma unroll
    for (int i = 0; i < 8; i++) {
        int qd = tid + i * 256; int r = qd >> 4, c = (qd & 15) * 4;
        float4 v = *(const float4*)(Qg + (size_t)r * Dh + c);
        uint2 hi, lo; split_bf16(v, hi, lo);
        uint32_t off = SWZ128((uint32_t)(r * 128 + c * 2));
        *(uint2*)(sm + off)         = hi;
        *(uint2*)(sm + 16384 + off) = lo;
    }
    __syncthreads();
    uint32_t qh[4][4], ql[4][4];
    {
        uint32_t arow = rb + (lane & 15);
        uint32_t ak   = (lane >> 4) * 8;
        #pragma unroll
        for (int kc = 0; kc < 4; kc++) {
            uint32_t off = SWZ128(arow * 128 + (kc * 16 + ak) * 2);
            ldsm4(qh[kc], su + off);
            ldsm4(ql[kc], su + 16384 + off);
        }
    }
    __syncthreads();   // all warps done reading Q before stage0 is refilled

    float4 ka[8], vv[8];
    auto loadK = [&](int n0) {
        #pragma unroll
        for (int i = 0; i < 8; i++) {
            int qd = tid + i * 256; int r = qd >> 4, c = (qd & 15) * 4;
            ka[i] = *(const float4*)(Kg + (size_t)(n0 + r) * Dh + c);
        }
    };
    auto storeK = [&](int s) {
        char* base = sm + s * 65536;
        #pragma unroll
        for (int i = 0; i < 8; i++) {
            int qd = tid + i * 256; int r = qd >> 4, c = (qd & 15) * 4;
            uint2 hi, lo; split_bf16(ka[i], hi, lo);
            uint32_t off = SWZ128((uint32_t)(r * 128 + c * 2));
            *(uint2*)(base + off)         = hi;
            *(uint2*)(base + 16384 + off) = lo;
        }
    };
    auto loadV = [&](int n0) {
        #pragma unroll
        for (int i = 0; i < 8; i++) {
            int qd = tid + i * 256; int r = qd >> 5, c = (qd & 31) * 4;
            vv[i] = *(const float4*)(Vg + (size_t)r * Lq + n0 + c);
        }
    };
    auto storeV = [&](int s) {
        char* base = sm + s * 65536 + 32768;
        #pragma unroll
        for (int i = 0; i < 8; i++) {
            int qd = tid + i * 256; int r = qd >> 5, c = (qd & 31) * 4;
            uint2 hi, lo; split_bf16(vv[i], hi, lo);
            uint32_t off = SWZ256((uint32_t)(r * 256 + c * 2));
            *(uint2*)(base + off)         = hi;
            *(uint2*)(base + 16384 + off) = lo;
        }
    };

    float o[8][4];
    #pragma unroll
    for (int f = 0; f < 8; f++) { o[f][0]=0.f; o[f][1]=0.f; o[f][2]=0.f; o[f][3]=0.f; }
    float mst0 = -3.4e38f, mst1 = -3.4e38f, sum0 = 0.f, sum1 = 0.f;

    const uint32_t brow = (lane & 7) + ((lane >> 4) & 1) * 8;
    const uint32_t bk8  = ((lane >> 3) & 1) * 8;
    const int l0 = m0 + rb + (lane >> 2), l1 = l0 + 8;
    const float L2E = 1.4426950408889634f;

    // preload stage 0
    loadK(0); storeK(0);
    loadV(0); storeV(0);
    __syncthreads();

    for (int nb = 0; nb < 8; nb++) {
        const int n0  = nb * 128;
        const int cur = nb & 1;
        const uint32_t suK  = su + cur * 65536;
        const uint32_t suKl = suK + 16384;
        const uint32_t suV  = suK + 32768;
        const uint32_t suVl = suK + 49152;

        if (nb < 7) loadK(n0 + 128);       // LDGs in flight over S-MMA

        // S = Q K^T (split x3)
        float s[16][4];
        #pragma unroll
        for (int f = 0; f < 16; f++) { s[f][0]=0.f; s[f][1]=0.f; s[f][2]=0.f; s[f][3]=0.f; }
        #pragma unroll
        for (int n16 = 0; n16 < 8; n16++) {
            #pragma unroll
            for (int kc = 0; kc < 4; kc++) {
                uint32_t off = SWZ128((n16 * 16 + brow) * 128 + (kc * 16 + bk8) * 2);
                uint32_t kh4[4], kl4[4];
                ldsm4(kh4, suK + off); ldsm4(kl4, suKl + off);
                mma_bf16(s[2*n16],   qh[kc], kh4[0], kh4[1]);
                mma_bf16(s[2*n16],   qh[kc], kl4[0], kl4[1]);
                mma_bf16(s[2*n16],   ql[kc], kh4[0], kh4[1]);
                mma_bf16(s[2*n16+1], qh[kc], kh4[2], kh4[3]);
                mma_bf16(s[2*n16+1], qh[kc], kl4[2], kl4[3]);
                mma_bf16(s[2*n16+1], ql[kc], kh4[2], kh4[3]);
            }
        }

        if (nb < 7) { storeK(cur ^ 1); loadV(n0 + 128); }

        // srel: s[l][m] += qe[l][1023 + m - l]  for m <= l
        if (n0 <= m0) {
            const float* q0 = g_qe + ((size_t)bh * Lq + l0) * Lq + (1023 - l0);
            const float* q1 = g_qe + ((size_t)bh * Lq + l1) * Lq + (1023 - l1);
            #pragma unroll
            for (int f = 0; f < 16; f++) {
                int m = n0 + f * 8 + (lane & 3) * 2;
                if (m < l0)       { s[f][0] += q0[m]; s[f][1] += q0[m + 1]; }
                else if (m == l0) { s[f][0] += q0[m]; }
                if (m < l1)       { s[f][2] += q1[m]; s[f][3] += q1[m + 1]; }
                else if (m == l1) { s[f][2] += q1[m]; }
            }
        }

        // online softmax (quad-local rows)
        float mx0 = -3.4e38f, mx1 = -3.4e38f;
        #pragma unroll
        for (int f = 0; f < 16; f++) {
            mx0 = fmaxf(mx0, fmaxf(s[f][0], s[f][1]));
            mx1 = fmaxf(mx1, fmaxf(s[f][2], s[f][3]));
        }
        mx0 = fmaxf(mx0, __shfl_xor_sync(0xffffffffu, mx0, 1));
        mx0 = fmaxf(mx0, __shfl_xor_sync(0xffffffffu, mx0, 2));
        mx1 = fmaxf(mx1, __shfl_xor_sync(0xffffffffu, mx1, 1));
        mx1 = fmaxf(mx1, __shfl_xor_sync(0xffffffffu, mx1, 2));
        float nm0 = fmaxf(mst0, mx0), nm1 = fmaxf(mst1, mx1);
        float sc0 = exp2f((mst0 - nm0) * L2E), sc1 = exp2f((mst1 - nm1) * L2E);
        mst0 = nm0; mst1 = nm1;
        sum0 *= sc0; sum1 *= sc1;
        #pragma unroll
        for (int f = 0; f < 8; f++) {
            o[f][0] *= sc0; o[f][1] *= sc0; o[f][2] *= sc1; o[f][3] *= sc1;
        }
        #pragma unroll
        for (int f = 0; f < 16; f++) {
            s[f][0] = exp2f((s[f][0] - nm0) * L2E);
            s[f][1] = exp2f((s[f][1] - nm0) * L2E);
            s[f][2] = exp2f((s[f][2] - nm1) * L2E);
            s[f][3] = exp2f((s[f][3] - nm1) * L2E);
            sum0 += s[f][0] + s[f][1];
            sum1 += s[f][2] + s[f][3];
        }

        if (nb < 7) storeV(cur ^ 1);

        // O += P V  (split x3)
        #pragma unroll
        for (int kk = 0; kk < 8; kk++) {
            uint32_t ahp[4], alp[4];
            {
                float p00 = s[2*kk][0],   p01 = s[2*kk][1];
                float p10 = s[2*kk][2],   p11 = s[2*kk][3];
                float p20 = s[2*kk+1][0], p21 = s[2*kk+1][1];
                float p30 = s[2*kk+1][2], p31 = s[2*kk+1][3];
                ahp[0] = packbf(p00, p01); ahp[1] = packbf(p10, p11);
                ahp[2] = packbf(p20, p21); ahp[3] = packbf(p30, p31);
                __nv_bfloat162 h;
                h = *(__nv_bfloat162*)&ahp[0];
                alp[0] = packbf(p00 - __low2float(h), p01 - __high2float(h));
                h = *(__nv_bfloat162*)&ahp[1];
                alp[1] = packbf(p10 - __low2float(h), p11 - __high2float(h));
                h = *(__nv_bfloat162*)&ahp[2];
                alp[2] = packbf(p20 - __low2float(h), p21 - __high2float(h));
                h = *(__nv_bfloat162*)&ahp[3];
                alp[3] = packbf(p30 - __low2float(h), p31 - __high2float(h));
            }
            #pragma unroll
            for (int n16 = 0; n16 < 4; n16++) {
                uint32_t off = SWZ256((n16 * 16 + brow) * 256 + (kk * 16 + bk8) * 2);
                uint32_t vh4[4], vl4[4];
                ldsm4(vh4, suV + off); ldsm4(vl4, suVl + off);
                mma_bf16(o[2*n16],   ahp, vh4[0], vh4[1]);
                mma_bf16(o[2*n16],   ahp, vl4[0], vl4[1]);
                mma_bf16(o[2*n16],   alp, vh4[0], vh4[1]);
                mma_bf16(o[2*n16+1], ahp, vh4[2], vh4[3]);
                mma_bf16(o[2*n16+1], ahp, vl4[2], vl4[3]);
                mma_bf16(o[2*n16+1], alp, vh4[2], vh4[3]);
            }
        }
        __syncthreads();
    }

    // finalize
    sum0 += __shfl_xor_sync(0xffffffffu, sum0, 1);
    sum0 += __shfl_xor_sync(0xffffffffu, sum0, 2);
    sum1 += __shfl_xor_sync(0xffffffffu, sum1, 1);
    sum1 += __shfl_xor_sync(0xffffffffu, sum1, 2);
    const float inv0 = 1.0f / sum0, inv1 = 1.0f / sum1;
    const int b = bh >> 4, h = bh & 15;
    #pragma unroll
    for (int f = 0; f < 8; f++) {
        int d = f * 8 + (lane & 3) * 2;
        float2 v0 = make_float2(o[f][0] * inv0, o[f][1] * inv0);
        float2 v1 = make_float2(o[f][2] * inv1, o[f][3] * inv1);
        *(float2*)(g_ctx + (size_t)l0 * (Bq * Eq) + b * Eq + h * Dh + d) = v0;
        *(float2*)(g_ctx + (size_t)l1 * (Bq * Eq) + b * Eq + h * Dh + d) = v1;
    }
}

__global__ __launch_bounds__(256, 1) void k_outproj(const float* __restrict__ W,
                                                    const float* __restrict__ bias,
                                                    float* __restrict__ out) {
    int m0 = blockIdx.y * 128, n0 = blockIdx.x * 128;
    EpiBias e{out, bias, m0, n0};
    mm_main<128>(g_ctx + (size_t)m0 * Eq, Eq, W + (size_t)n0 * Eq, Eq, Eq, e);
}

// ---------------------------------------------------------------------------
extern "C" void kernel_launch(void* const* d_in, const int* in_sizes, int n_in,
                              void* d_out, int out_size)
{
    (void)in_sizes; (void)n_in; (void)out_size;
    const float* query  = (const float*)d_in[0];
    const float* relpos = (const float*)d_in[1];
    const float* w_in   = (const float*)d_in[2];
    const float* b_in   = (const float*)d_in[3];
    const float* w_out  = (const float*)d_in[4];
    const float* b_out  = (const float*)d_in[5];
    float* out = (float*)d_out;

    const int SMG = 2 * (16384 + 2 * 128 * 64);   // 65536 for NT=128
    cudaFuncSetAttribute(k_qkv,     cudaFuncAttributeMaxDynamicSharedMemorySize, SMG);
    cudaFuncSetAttribute(k_qe,      cudaFuncAttributeMaxDynamicSharedMemorySize, SMG);
    cudaFuncSetAttribute(k_outproj, cudaFuncAttributeMaxDynamicSharedMemorySize, SMG);
    cudaFuncSetAttribute(k_attn,    cudaFuncAttributeMaxDynamicSharedMemorySize, 131072);

    k_qkv    <<<dim3(24, 32),   256, SMG>>>(query, w_in, b_in);
    k_qe     <<<dim3(8, 8, 64), 256, SMG>>>(relpos);
    k_attn   <<<dim3(8, 64),    256, 131072>>>();
    k_outproj<<<dim3(8, 32),    256, SMG>>>(w_out, b_out, out);
}

// round 9
// speedup vs baseline: 1.0083x; 1.0083x over previous
#include <cuda_runtime.h>
#include <cuda_bf16.h>
#include <stdint.h>

#define NH 16
#define Dh 64
#define Lq 1024
#define Bq 4
#define Eq 1024
#define BH 64

// ---- scratch (device globals) ----
__device__ float g_q[BH*Lq*Dh];          // (BH,L,D), q pre-scaled by 1/8
__device__ float g_k[BH*Lq*Dh];          // (BH,L,D)
__device__ float g_v[BH*Lq*Dh];          // (BH,D,L)  TRANSPOSED for PV
__device__ float g_qe[(size_t)BH*Lq*Lq]; // relpos logits (band tiles only)
__device__ float g_ctx[Lq*Bq*Eq];        // (L,B,E)

#define SWZ64(x)  ((x) ^ (((x) >> 3) & 0x30))
#define SWZ128(x) ((x) ^ (((x) >> 3) & 0x70))
#define SWZ256(x) ((x) ^ (((x) >> 4) & 0x70))

__device__ __forceinline__ void ldsm4(uint32_t (&r)[4], uint32_t addr) {
    asm volatile("ldmatrix.sync.aligned.m8n8.x4.shared.b16 {%0,%1,%2,%3}, [%4];"
                 : "=r"(r[0]), "=r"(r[1]), "=r"(r[2]), "=r"(r[3]) : "r"(addr));
}
__device__ __forceinline__ void mma_bf16(float (&d)[4], const uint32_t (&a)[4],
                                         uint32_t b0, uint32_t b1) {
    asm volatile("mma.sync.aligned.m16n8k16.row.col.f32.bf16.bf16.f32 "
                 "{%0,%1,%2,%3}, {%4,%5,%6,%7}, {%8,%9}, {%0,%1,%2,%3};"
                 : "+f"(d[0]), "+f"(d[1]), "+f"(d[2]), "+f"(d[3])
                 : "r"(a[0]), "r"(a[1]), "r"(a[2]), "r"(a[3]), "r"(b0), "r"(b1));
}
__device__ __forceinline__ void split_bf16(float4 v, uint2& hi, uint2& lo) {
    __nv_bfloat162 h0 = __floats2bfloat162_rn(v.x, v.y);
    __nv_bfloat162 h1 = __floats2bfloat162_rn(v.z, v.w);
    __nv_bfloat162 l0 = __floats2bfloat162_rn(v.x - __low2float(h0),  v.y - __high2float(h0));
    __nv_bfloat162 l1 = __floats2bfloat162_rn(v.z - __low2float(h1),  v.w - __high2float(h1));
    hi = make_uint2(*(uint32_t*)&h0, *(uint32_t*)&h1);
    lo = make_uint2(*(uint32_t*)&l0, *(uint32_t*)&l1);
}
__device__ __forceinline__ uint32_t packbf(float a, float b) {
    __nv_bfloat162 t = __floats2bfloat162_rn(a, b);
    return *(uint32_t*)&t;
}

// ---------------------------------------------------------------------------
// Double-buffered GEMM: C(128 x NT) = A(128 x K) * B(NT x K)^T
// 256 thr, warp grid 2x4. Dynamic smem: 2 stages of (A 16KB + B NT*128 B).
// One __syncthreads per 32-K iteration; LDG for next stage in flight over MMA.
// ---------------------------------------------------------------------------
template<int NT, class Epi>
__device__ __forceinline__ void mm_main(const float* __restrict__ A, int lda,
                                        const float* __restrict__ B, int ldb,
                                        int K, Epi epi)
{
    constexpr int WN   = NT / 4;
    constexpr int NTN8 = WN / 8;
    constexpr int NB16 = WN / 16;
    constexpr int BI   = NT / 32;
    constexpr int ASZ  = 8192;         // 128 x 32 bf16
    constexpr int BSZ  = NT * 64;      // NT x 32 bf16
    constexpr int STG  = 2 * ASZ + 2 * BSZ;

    extern __shared__ char dsm[];
    const uint32_t su = (uint32_t)__cvta_generic_to_shared(dsm);

    const int tid  = threadIdx.x;
    const int lane = tid & 31, w = tid >> 5;
    const int m_base = (w & 1) * 64;
    const int n_base = (w >> 1) * WN;

    float acc[4][NTN8][4];
    #pragma unroll
    for (int i = 0; i < 4; i++)
        #pragma unroll
        for (int j = 0; j < NTN8; j++)
            #pragma unroll
            for (int q = 0; q < 4; q++) acc[i][j][q] = 0.f;

    const uint32_t a_row = lane & 15;
    const uint32_t a_k8  = (lane >> 4) * 8;
    const uint32_t b_row = (lane & 7) + ((lane >> 4) & 1) * 8;
    const uint32_t b_k8  = ((lane >> 3) & 1) * 8;

    float4 va[4], vb[BI];

    auto gload = [&](int kb) {
        #pragma unroll
        for (int i = 0; i < 4; i++) {
            int qd = tid + i * 256; int r = qd >> 3, c = (qd & 7) * 4;
            va[i] = *(const float4*)(A + (size_t)r * lda + kb + c);
        }
        #pragma unroll
        for (int i = 0; i < BI; i++) {
            int qd = tid + i * 256; int r = qd >> 3, c = (qd & 7) * 4;
            vb[i] = *(const float4*)(B + (size_t)r * ldb + kb + c);
        }
    };
    auto sstore = [&](int s) {
        char* base = dsm + s * STG;
        #pragma unroll
        for (int i = 0; i < 4; i++) {
            int qd = tid + i * 256; int r = qd >> 3, c = (qd & 7) * 4;
            uint2 hi, lo; split_bf16(va[i], hi, lo);
            uint32_t off = SWZ64((uint32_t)(r * 64 + c * 2));
            *(uint2*)(base + off)       = hi;
            *(uint2*)(base + ASZ + off) = lo;
        }
        #pragma unroll
        for (int i = 0; i < BI; i++) {
            int qd = tid + i * 256; int r = qd >> 3, c = (qd & 7) * 4;
            uint2 hi, lo; split_bf16(vb[i], hi, lo);
            uint32_t off = SWZ64((uint32_t)(r * 64 + c * 2));
            *(uint2*)(base + 2 * ASZ + off)       = hi;
            *(uint2*)(base + 2 * ASZ + BSZ + off) = lo;
        }
    };
    auto domma = [&](int s) {
        const uint32_t sbA  = su + s * STG;
        const uint32_t sbAl = sbA + ASZ;
        const uint32_t sbB  = sbA + 2 * ASZ;
        const uint32_t sbBl = sbB + BSZ;
        #pragma unroll
        for (int kc = 0; kc < 2; kc++) {
            uint32_t ah[4][4], al[4][4];
            #pragma unroll
            for (int mt = 0; mt < 4; mt++) {
                uint32_t off = SWZ64((uint32_t)((m_base + mt * 16 + a_row) * 64
                                                + (kc * 16 + a_k8) * 2));
                ldsm4(ah[mt], sbA  + off);
                ldsm4(al[mt], sbAl + off);
            }
            uint32_t bh[NB16][4], bl[NB16][4];
            #pragma unroll
            for (int nb = 0; nb < NB16; nb++) {
                uint32_t off = SWZ64((uint32_t)((n_base + nb * 16 + b_row) * 64
                                                + (kc * 16 + b_k8) * 2));
                ldsm4(bh[nb], sbB  + off);
                ldsm4(bl[nb], sbBl + off);
            }
            #pragma unroll
            for (int mt = 0; mt < 4; mt++)
                #pragma unroll
                for (int nt = 0; nt < NTN8; nt++) {
                    uint32_t b0h = bh[nt >> 1][(nt & 1) * 2];
                    uint32_t b1h = bh[nt >> 1][(nt & 1) * 2 + 1];
                    uint32_t b0l = bl[nt >> 1][(nt & 1) * 2];
                    uint32_t b1l = bl[nt >> 1][(nt & 1) * 2 + 1];
                    mma_bf16(acc[mt][nt], ah[mt], b0h, b1h);
                    mma_bf16(acc[mt][nt], ah[mt], b0l, b1l);
                    mma_bf16(acc[mt][nt], al[mt], b0h, b1h);
                }
        }
    };

    gload(0); sstore(0); __syncthreads();
    const int nk = K >> 5;
    for (int i = 0; i < nk; i++) {
        if (i + 1 < nk) gload((i + 1) << 5);   // LDGs in flight over MMA
        domma(i & 1);
        if (i + 1 < nk) sstore((i + 1) & 1);
        __syncthreads();
    }

    #pragma unroll
    for (int mt = 0; mt < 4; mt++)
        #pragma unroll
        for (int nt = 0; nt < NTN8; nt++) {
            int m = m_base + mt * 16 + (lane >> 2);
            int n = n_base + nt * 8 + (lane & 3) * 2;
            epi(m,     n, make_float2(acc[mt][nt][0], acc[mt][nt][1]));
            epi(m + 8, n, make_float2(acc[mt][nt][2], acc[mt][nt][3]));
        }
}

// ---------------------------------------------------------------------------
// Epilogues
// ---------------------------------------------------------------------------
struct EpiQKV {
    int m0, n0; const float* bias;
    __device__ __forceinline__ void operator()(int mi, int ni, float2 v) const {
        int m = m0 + mi, n = n0 + ni;
        float2 bb = *(const float2*)(bias + n);
        v.x += bb.x; v.y += bb.y;
        int l = m >> 2, b = m & 3;
        int sec = n >> 10, e = n & 1023, h = e >> 6, d = e & 63;
        if (sec == 0) {
            v.x *= 0.125f; v.y *= 0.125f;
            *(float2*)(g_q + (((b * NH + h) * Lq + l) * Dh + d)) = v;
        } else if (sec == 1) {
            *(float2*)(g_k + (((b * NH + h) * Lq + l) * Dh + d)) = v;
        } else {
            size_t idx = ((size_t)(b * NH + h) * Dh + d) * Lq + l;
            g_v[idx]      = v.x;
            g_v[idx + Lq] = v.y;
        }
    }
};
struct EpiStore {
    float* C; int m0, n0;
    __device__ __forceinline__ void operator()(int mi, int ni, float2 v) const {
        *(float2*)(C + (size_t)(m0 + mi) * Lq + (n0 + ni)) = v;
    }
};
struct EpiBias {
    float* C; const float* bias; int m0, n0;
    __device__ __forceinline__ void operator()(int mi, int ni, float2 v) const {
        float2 bb = *(const float2*)(bias + n0 + ni);
        v.x += bb.x; v.y += bb.y;
        *(float2*)(C + (size_t)(m0 + mi) * Eq + (n0 + ni)) = v;
    }
};

// ---------------------------------------------------------------------------
__global__ __launch_bounds__(256, 1) void k_qkv(const float* __restrict__ q,
                                                const float* __restrict__ W,
                                                const float* __restrict__ bias) {
    EpiQKV e{(int)blockIdx.y * 128, (int)blockIdx.x * 128, bias};
    mm_main<128>(q + (size_t)e.m0 * Eq, Eq, W + (size_t)e.n0 * Eq, Eq, Eq, e);
}

__global__ __launch_bounds__(256, 1) void k_qe(const float* __restrict__ er) {
    if (blockIdx.x + blockIdx.y < 7) return;   // band tiles only
    int bh = blockIdx.z;
    int m0 = blockIdx.y * 128, n0 = blockIdx.x * 128;
    EpiStore e{g_qe + (size_t)bh * Lq * Lq, m0, n0};
    mm_main<128>(g_q + (size_t)bh * Lq * Dh + (size_t)m0 * Dh, Dh,
                 er + (size_t)n0 * Dh, Dh, Dh, e);
}

// ---------------------------------------------------------------------------
// Fused attention, double-buffered K/V stages (2 x 64KB dynamic smem)
// ---------------------------------------------------------------------------
__global__ __launch_bounds__(256, 1) void k_attn() {
    extern __shared__ char sm[];
    const uint32_t su = (uint32_t)__cvta_generic_to_shared(sm);
    // stage s: Kh = s*65536, Kl = +16384, Vh = +32768, Vl = +49152

    const int tid = threadIdx.x, lane = tid & 31, w = tid >> 5;
    const int m0 = blockIdx.x * 128, bh = blockIdx.y;
    const int rb = w * 16;

    const float* __restrict__ Qg = g_q + (size_t)bh * Lq * Dh + (size_t)m0 * Dh;
    const float* __restrict__ Kg = g_k + (size_t)bh * Lq * Dh;
    const float* __restrict__ Vg = g_v + (size_t)bh * Dh * Lq;   // (D, L)

    // ---- stage Q through stage0 K area, pull A-frags to registers ----
    #pragma unroll
    for (int i = 0; i < 8; i++) {
        int qd = tid + i * 256; int r = qd >> 4, c = (qd & 15) * 4;
        float4 v = *(const float4*)(Qg + (size_t)r * Dh + c);
        uint2 hi, lo; split_bf16(v, hi, lo);
        uint32_t off = SWZ128((uint32_t)(r * 128 + c * 2));
        *(uint2*)(sm + off)         = hi;
        *(uint2*)(sm + 16384 + off) = lo;
    }
    __syncthreads();
    uint32_t qh[4][4], ql[4][4];
    {
        uint32_t arow = rb + (lane & 15);
        uint32_t ak   = (lane >> 4) * 8;
        #pragma unroll
        for (int kc = 0; kc < 4; kc++) {
            uint32_t off = SWZ128(arow * 128 + (kc * 16 + ak) * 2);
            ldsm4(qh[kc], su + off);
            ldsm4(ql[kc], su + 16384 + off);
        }
    }
    __syncthreads();   // all warps done reading Q before stage0 is refilled

    float4 ka[8], vv[8];
    auto loadK = [&](int n0) {
        #pragma unroll
        for (int i = 0; i < 8; i++) {
            int qd = tid + i * 256; int r = qd >> 4, c = (qd & 15) * 4;
            ka[i] = *(const float4*)(Kg + (size_t)(n0 + r) * Dh + c);
        }
    };
    auto storeK = [&](int s) {
        char* base = sm + s * 65536;
        #pragma unroll
        for (int i = 0; i < 8; i++) {
            int qd = tid + i * 256; int r = qd >> 4, c = (qd & 15) * 4;
            uint2 hi, lo; split_bf16(ka[i], hi, lo);
            uint32_t off = SWZ128((uint32_t)(r * 128 + c * 2));
            *(uint2*)(base + off)         = hi;
            *(uint2*)(base + 16384 + off) = lo;
        }
    };
    auto loadV = [&](int n0) {
        #pragma unroll
        for (int i = 0; i < 8; i++) {
            int qd = tid + i * 256; int r = qd >> 5, c = (qd & 31) * 4;
            vv[i] = *(const float4*)(Vg + (size_t)r * Lq + n0 + c);
        }
    };
    auto storeV = [&](int s) {
        char* base = sm + s * 65536 + 32768;
        #pragma unroll
        for (int i = 0; i < 8; i++) {
            int qd = tid + i * 256; int r = qd >> 5, c = (qd & 31) * 4;
            uint2 hi, lo; split_bf16(vv[i], hi, lo);
            uint32_t off = SWZ256((uint32_t)(r * 256 + c * 2));
            *(uint2*)(base + off)         = hi;
            *(uint2*)(base + 16384 + off) = lo;
        }
    };

    float o[8][4];
    #pragma unroll
    for (int f = 0; f < 8; f++) { o[f][0]=0.f; o[f][1]=0.f; o[f][2]=0.f; o[f][3]=0.f; }
    float mst0 = -3.4e38f, mst1 = -3.4e38f, sum0 = 0.f, sum1 = 0.f;

    const uint32_t brow = (lane & 7) + ((lane >> 4) & 1) * 8;
    const uint32_t bk8  = ((lane >> 3) & 1) * 8;
    const int l0 = m0 + rb + (lane >> 2), l1 = l0 + 8;
    const float L2E = 1.4426950408889634f;

    // preload stage 0
    loadK(0); storeK(0);
    loadV(0); storeV(0);
    __syncthreads();

    for (int nb = 0; nb < 8; nb++) {
        const int n0  = nb * 128;
        const int cur = nb & 1;
        const uint32_t suK  = su + cur * 65536;
        const uint32_t suKl = suK + 16384;
        const uint32_t suV  = suK + 32768;
        const uint32_t suVl = suK + 49152;

        if (nb < 7) loadK(n0 + 128);       // LDGs in flight over S-MMA

        // S = Q K^T (split x3)
        float s[16][4];
        #pragma unroll
        for (int f = 0; f < 16; f++) { s[f][0]=0.f; s[f][1]=0.f; s[f][2]=0.f; s[f][3]=0.f; }
        #pragma unroll
        for (int n16 = 0; n16 < 8; n16++) {
            #pragma unroll
            for (int kc = 0; kc < 4; kc++) {
                uint32_t off = SWZ128((n16 * 16 + brow) * 128 + (kc * 16 + bk8) * 2);
                uint32_t kh4[4], kl4[4];
                ldsm4(kh4, suK + off); ldsm4(kl4, suKl + off);
                mma_bf16(s[2*n16],   qh[kc], kh4[0], kh4[1]);
                mma_bf16(s[2*n16],   qh[kc], kl4[0], kl4[1]);
                mma_bf16(s[2*n16],   ql[kc], kh4[0], kh4[1]);
                mma_bf16(s[2*n16+1], qh[kc], kh4[2], kh4[3]);
                mma_bf16(s[2*n16+1], qh[kc], kl4[2], kl4[3]);
                mma_bf16(s[2*n16+1], ql[kc], kh4[2], kh4[3]);
            }
        }

        if (nb < 7) { storeK(cur ^ 1); loadV(n0 + 128); }

        // srel: s[l][m] += qe[l][1023 + m - l]  for m <= l
        if (n0 <= m0) {
            const float* q0 = g_qe + ((size_t)bh * Lq + l0) * Lq + (1023 - l0);
            const float* q1 = g_qe + ((size_t)bh * Lq + l1) * Lq + (1023 - l1);
            #pragma unroll
            for (int f = 0; f < 16; f++) {
                int m = n0 + f * 8 + (lane & 3) * 2;
                if (m < l0)       { s[f][0] += q0[m]; s[f][1] += q0[m + 1]; }
                else if (m == l0) { s[f][0] += q0[m]; }
                if (m < l1)       { s[f][2] += q1[m]; s[f][3] += q1[m + 1]; }
                else if (m == l1) { s[f][2] += q1[m]; }
            }
        }

        // online softmax (quad-local rows)
        float mx0 = -3.4e38f, mx1 = -3.4e38f;
        #pragma unroll
        for (int f = 0; f < 16; f++) {
            mx0 = fmaxf(mx0, fmaxf(s[f][0], s[f][1]));
            mx1 = fmaxf(mx1, fmaxf(s[f][2], s[f][3]));
        }
        mx0 = fmaxf(mx0, __shfl_xor_sync(0xffffffffu, mx0, 1));
        mx0 = fmaxf(mx0, __shfl_xor_sync(0xffffffffu, mx0, 2));
        mx1 = fmaxf(mx1, __shfl_xor_sync(0xffffffffu, mx1, 1));
        mx1 = fmaxf(mx1, __shfl_xor_sync(0xffffffffu, mx1, 2));
        float nm0 = fmaxf(mst0, mx0), nm1 = fmaxf(mst1, mx1);
        float sc0 = exp2f((mst0 - nm0) * L2E), sc1 = exp2f((mst1 - nm1) * L2E);
        mst0 = nm0; mst1 = nm1;
        sum0 *= sc0; sum1 *= sc1;
        #pragma unroll
        for (int f = 0; f < 8; f++) {
            o[f][0] *= sc0; o[f][1] *= sc0; o[f][2] *= sc1; o[f][3] *= sc1;
        }
        #pragma unroll
        for (int f = 0; f < 16; f++) {
            s[f][0] = exp2f((s[f][0] - nm0) * L2E);
            s[f][1] = exp2f((s[f][1] - nm0) * L2E);
            s[f][2] = exp2f((s[f][2] - nm1) * L2E);
            s[f][3] = exp2f((s[f][3] - nm1) * L2E);
            sum0 += s[f][0] + s[f][1];
            sum1 += s[f][2] + s[f][3];
        }

        if (nb < 7) storeV(cur ^ 1);

        // O += P V  (split x3)
        #pragma unroll
        for (int kk = 0; kk < 8; kk++) {
            uint32_t ahp[4], alp[4];
            {
                float p00 = s[2*kk][0],   p01 = s[2*kk][1];
                float p10 = s[2*kk][2],   p11 = s[2*kk][3];
                float p20 = s[2*kk+1][0], p21 = s[2*kk+1][1];
                float p30 = s[2*kk+1][2], p31 = s[2*kk+1][3];
                ahp[0] = packbf(p00, p01); ahp[1] = packbf(p10, p11);
                ahp[2] = packbf(p20, p21); ahp[3] = packbf(p30, p31);
                __nv_bfloat162 h;
                h = *(__nv_bfloat162*)&ahp[0];
                alp[0] = packbf(p00 - __low2float(h), p01 - __high2float(h));
                h = *(__nv_bfloat162*)&ahp[1];
                alp[1] = packbf(p10 - __low2float(h), p11 - __high2float(h));
                h = *(__nv_bfloat162*)&ahp[2];
                alp[2] = packbf(p20 - __low2float(h), p21 - __high2float(h));
                h = *(__nv_bfloat162*)&ahp[3];
                alp[3] = packbf(p30 - __low2float(h), p31 - __high2float(h));
            }
            #pragma unroll
            for (int n16 = 0; n16 < 4; n16++) {
                uint32_t off = SWZ256((n16 * 16 + brow) * 256 + (kk * 16 + bk8) * 2);
                uint32_t vh4[4], vl4[4];
                ldsm4(vh4, suV + off); ldsm4(vl4, suVl + off);
                mma_bf16(o[2*n16],   ahp, vh4[0], vh4[1]);
                mma_bf16(o[2*n16],   ahp, vl4[0], vl4[1]);
                mma_bf16(o[2*n16],   alp, vh4[0], vh4[1]);
                mma_bf16(o[2*n16+1], ahp, vh4[2], vh4[3]);
                mma_bf16(o[2*n16+1], ahp, vl4[2], vl4[3]);
                mma_bf16(o[2*n16+1], alp, vh4[2], vh4[3]);
            }
        }
        __syncthreads();
    }

    // finalize
    sum0 += __shfl_xor_sync(0xffffffffu, sum0, 1);
    sum0 += __shfl_xor_sync(0xffffffffu, sum0, 2);
    sum1 += __shfl_xor_sync(0xffffffffu, sum1, 1);
    sum1 += __shfl_xor_sync(0xffffffffu, sum1, 2);
    const float inv0 = 1.0f / sum0, inv1 = 1.0f / sum1;
    const int b = bh >> 4, h = bh & 15;
    #pragma unroll
    for (int f = 0; f < 8; f++) {
        int d = f * 8 + (lane & 3) * 2;
        float2 v0 = make_float2(o[f][0] * inv0, o[f][1] * inv0);
        float2 v1 = make_float2(o[f][2] * inv1, o[f][3] * inv1);
        *(float2*)(g_ctx + (size_t)l0 * (Bq * Eq) + b * Eq + h * Dh + d) = v0;
        *(float2*)(g_ctx + (size_t)l1 * (Bq * Eq) + b * Eq + h * Dh + d) = v1;
    }
}

__global__ __launch_bounds__(256, 1) void k_outproj(const float* __restrict__ W,
                                                    const float* __restrict__ bias,
                                                    float* __restrict__ out) {
    int m0 = blockIdx.y * 128, n0 = blockIdx.x * 128;
    EpiBias e{out, bias, m0, n0};
    mm_main<128>(g_ctx + (size_t)m0 * Eq, Eq, W + (size_t)n0 * Eq, Eq, Eq, e);
}

// ---------------------------------------------------------------------------
extern "C" void kernel_launch(void* const* d_in, const int* in_sizes, int n_in,
                              void* d_out, int out_size)
{
    (void)in_sizes; (void)n_in; (void)out_size;
    const float* query  = (const float*)d_in[0];
    const float* relpos = (const float*)d_in[1];
    const float* w_in   = (const float*)d_in[2];
    const float* b_in   = (const float*)d_in[3];
    const float* w_out  = (const float*)d_in[4];
    const float* b_out  = (const float*)d_in[5];
    float* out = (float*)d_out;

    const int SMG = 2 * (16384 + 2 * 128 * 64);   // 65536 for NT=128
    cudaFuncSetAttribute(k_qkv,     cudaFuncAttributeMaxDynamicSharedMemorySize, SMG);
    cudaFuncSetAttribute(k_qe,      cudaFuncAttributeMaxDynamicSharedMemorySize, SMG);
    cudaFuncSetAttribute(k_outproj, cudaFuncAttributeMaxDynamicSharedMemorySize, SMG);
    cudaFuncSetAttribute(k_attn,    cudaFuncAttributeMaxDynamicSharedMemorySize, 131072);

    k_qkv    <<<dim3(24, 32),   256, SMG>>>(query, w_in, b_in);
    k_qe     <<<dim3(8, 8, 64), 256, SMG>>>(relpos);
    k_attn   <<<dim3(8, 64),    256, 131072>>>();
    k_outproj<<<dim3(8, 32),    256, SMG>>>(w_out, b_out, out);
}

// round 10
// speedup vs baseline: 1.1358x; 1.1265x over previous
#include <cuda_runtime.h>
#include <cuda_fp16.h>
#include <stdint.h>

#define NH 16
#define Dh 64
#define Lq 1024
#define Bq 4
#define Eq 1024
#define BH 64

// ---- scratch (device globals) ----
__device__ float g_q[BH*Lq*Dh];          // (BH,L,D), q pre-scaled by 1/8
__device__ float g_k[BH*Lq*Dh];          // (BH,L,D)
__device__ float g_v[BH*Lq*Dh];          // (BH,D,L)  TRANSPOSED for PV
__device__ float g_qe[(size_t)BH*Lq*Lq]; // relpos logits (band tiles only)
__device__ float g_ctx[Lq*Bq*Eq];        // (L,B,E)

#define SWZ64(x)  ((x) ^ (((x) >> 3) & 0x30))
#define SWZ128(x) ((x) ^ (((x) >> 3) & 0x70))
#define SWZ256(x) ((x) ^ (((x) >> 4) & 0x70))

__device__ __forceinline__ void ldsm4(uint32_t (&r)[4], uint32_t addr) {
    asm volatile("ldmatrix.sync.aligned.m8n8.x4.shared.b16 {%0,%1,%2,%3}, [%4];"
                 : "=r"(r[0]), "=r"(r[1]), "=r"(r[2]), "=r"(r[3]) : "r"(addr));
}
__device__ __forceinline__ void mma_f16(float (&d)[4], const uint32_t (&a)[4],
                                        uint32_t b0, uint32_t b1) {
    asm volatile("mma.sync.aligned.m16n8k16.row.col.f32.f16.f16.f32 "
                 "{%0,%1,%2,%3}, {%4,%5,%6,%7}, {%8,%9}, {%0,%1,%2,%3};"
                 : "+f"(d[0]), "+f"(d[1]), "+f"(d[2]), "+f"(d[3])
                 : "r"(a[0]), "r"(a[1]), "r"(a[2]), "r"(a[3]), "r"(b0), "r"(b1));
}
__device__ __forceinline__ uint2 pack4_f16(float4 v) {
    __half2 h0 = __floats2half2_rn(v.x, v.y);
    __half2 h1 = __floats2half2_rn(v.z, v.w);
    return make_uint2(*(uint32_t*)&h0, *(uint32_t*)&h1);
}
__device__ __forceinline__ void split_f16(float4 v, uint2& hi, uint2& lo) {
    __half2 h0 = __floats2half2_rn(v.x, v.y);
    __half2 h1 = __floats2half2_rn(v.z, v.w);
    __half2 l0 = __floats2half2_rn(v.x - __low2float(h0),  v.y - __high2float(h0));
    __half2 l1 = __floats2half2_rn(v.z - __low2float(h1),  v.w - __high2float(h1));
    hi = make_uint2(*(uint32_t*)&h0, *(uint32_t*)&h1);
    lo = make_uint2(*(uint32_t*)&l0, *(uint32_t*)&l1);
}
__device__ __forceinline__ uint32_t packh(float a, float b) {
    __half2 t = __floats2half2_rn(a, b);
    return *(uint32_t*)&t;
}

// ---------------------------------------------------------------------------
// Double-buffered GEMM: C(128 x NT) = A(128 x K) * B(NT x K)^T
// fp16 x2: A rounded to fp16, B split hi/lo. 256 thr, warp grid 2x4.
// Dynamic smem: 2 stages of (A 8KB + B 2*NT*64B). One sync per 32-K iter.
// ---------------------------------------------------------------------------
template<int NT, class Epi>
__device__ __forceinline__ void mm_main(const float* __restrict__ A, int lda,
                                        const float* __restrict__ B, int ldb,
                                        int K, Epi epi)
{
    constexpr int WN   = NT / 4;
    constexpr int NTN8 = WN / 8;
    constexpr int NB16 = WN / 16;
    constexpr int BI   = NT / 32;
    constexpr int ASZ  = 8192;           // 128 x 32 fp16 (hi only)
    constexpr int BSZ  = NT * 64;        // NT x 32 fp16
    constexpr int STG  = ASZ + 2 * BSZ;

    extern __shared__ char dsm[];
    const uint32_t su = (uint32_t)__cvta_generic_to_shared(dsm);

    const int tid  = threadIdx.x;
    const int lane = tid & 31, w = tid >> 5;
    const int m_base = (w & 1) * 64;
    const int n_base = (w >> 1) * WN;

    float acc[4][NTN8][4];
    #pragma unroll
    for (int i = 0; i < 4; i++)
        #pragma unroll
        for (int j = 0; j < NTN8; j++)
            #pragma unroll
            for (int q = 0; q < 4; q++) acc[i][j][q] = 0.f;

    const uint32_t a_row = lane & 15;
    const uint32_t a_k8  = (lane >> 4) * 8;
    const uint32_t b_row = (lane & 7) + ((lane >> 4) & 1) * 8;
    const uint32_t b_k8  = ((lane >> 3) & 1) * 8;

    float4 va[4], vb[BI];

    auto gload = [&](int kb) {
        #pragma unroll
        for (int i = 0; i < 4; i++) {
            int qd = tid + i * 256; int r = qd >> 3, c = (qd & 7) * 4;
            va[i] = *(const float4*)(A + (size_t)r * lda + kb + c);
        }
        #pragma unroll
        for (int i = 0; i < BI; i++) {
            int qd = tid + i * 256; int r = qd >> 3, c = (qd & 7) * 4;
            vb[i] = *(const float4*)(B + (size_t)r * ldb + kb + c);
        }
    };
    auto sstore = [&](int s) {
        char* base = dsm + s * STG;
        #pragma unroll
        for (int i = 0; i < 4; i++) {
            int qd = tid + i * 256; int r = qd >> 3, c = (qd & 7) * 4;
            uint32_t off = SWZ64((uint32_t)(r * 64 + c * 2));
            *(uint2*)(base + off) = pack4_f16(va[i]);
        }
        #pragma unroll
        for (int i = 0; i < BI; i++) {
            int qd = tid + i * 256; int r = qd >> 3, c = (qd & 7) * 4;
            uint2 hi, lo; split_f16(vb[i], hi, lo);
            uint32_t off = SWZ64((uint32_t)(r * 64 + c * 2));
            *(uint2*)(base + ASZ + off)       = hi;
            *(uint2*)(base + ASZ + BSZ + off) = lo;
        }
    };
    auto domma = [&](int s) {
        const uint32_t sbA  = su + s * STG;
        const uint32_t sbB  = sbA + ASZ;
        const uint32_t sbBl = sbB + BSZ;
        #pragma unroll
        for (int kc = 0; kc < 2; kc++) {
            uint32_t ah[4][4];
            #pragma unroll
            for (int mt = 0; mt < 4; mt++) {
                uint32_t off = SWZ64((uint32_t)((m_base + mt * 16 + a_row) * 64
                                                + (kc * 16 + a_k8) * 2));
                ldsm4(ah[mt], sbA + off);
            }
            uint32_t bh[NB16][4], bl[NB16][4];
            #pragma unroll
            for (int nb = 0; nb < NB16; nb++) {
                uint32_t off = SWZ64((uint32_t)((n_base + nb * 16 + b_row) * 64
                                                + (kc * 16 + b_k8) * 2));
                ldsm4(bh[nb], sbB  + off);
                ldsm4(bl[nb], sbBl + off);
            }
            #pragma unroll
            for (int mt = 0; mt < 4; mt++)
                #pragma unroll
                for (int nt = 0; nt < NTN8; nt++) {
                    uint32_t b0h = bh[nt >> 1][(nt & 1) * 2];
                    uint32_t b1h = bh[nt >> 1][(nt & 1) * 2 + 1];
                    uint32_t b0l = bl[nt >> 1][(nt & 1) * 2];
                    uint32_t b1l = bl[nt >> 1][(nt & 1) * 2 + 1];
                    mma_f16(acc[mt][nt], ah[mt], b0h, b1h);
                    mma_f16(acc[mt][nt], ah[mt], b0l, b1l);
                }
        }
    };

    gload(0); sstore(0); __syncthreads();
    const int nk = K >> 5;
    for (int i = 0; i < nk; i++) {
        if (i + 1 < nk) gload((i + 1) << 5);
        domma(i & 1);
        if (i + 1 < nk) sstore((i + 1) & 1);
        __syncthreads();
    }

    #pragma unroll
    for (int mt = 0; mt < 4; mt++)
        #pragma unroll
        for (int nt = 0; nt < NTN8; nt++) {
            int m = m_base + mt * 16 + (lane >> 2);
            int n = n_base + nt * 8 + (lane & 3) * 2;
            epi(m,     n, make_float2(acc[mt][nt][0], acc[mt][nt][1]));
            epi(m + 8, n, make_float2(acc[mt][nt][2], acc[mt][nt][3]));
        }
}

// ---------------------------------------------------------------------------
// Epilogues
// ---------------------------------------------------------------------------
struct EpiQKV {
    int m0, n0; const float* bias;
    __device__ __forceinline__ void operator()(int mi, int ni, float2 v) const {
        int m = m0 + mi, n = n0 + ni;
        float2 bb = *(const float2*)(bias + n);
        v.x += bb.x; v.y += bb.y;
        int l = m >> 2, b = m & 3;
        int sec = n >> 10, e = n & 1023, h = e >> 6, d = e & 63;
        if (sec == 0) {
            v.x *= 0.125f; v.y *= 0.125f;
            *(float2*)(g_q + (((b * NH + h) * Lq + l) * Dh + d)) = v;
        } else if (sec == 1) {
            *(float2*)(g_k + (((b * NH + h) * Lq + l) * Dh + d)) = v;
        } else {
            size_t idx = ((size_t)(b * NH + h) * Dh + d) * Lq + l;
            g_v[idx]      = v.x;
            g_v[idx + Lq] = v.y;
        }
    }
};
struct EpiStore {
    float* C; int m0, n0;
    __device__ __forceinline__ void operator()(int mi, int ni, float2 v) const {
        *(float2*)(C + (size_t)(m0 + mi) * Lq + (n0 + ni)) = v;
    }
};
struct EpiBias {
    float* C; const float* bias; int m0, n0;
    __device__ __forceinline__ void operator()(int mi, int ni, float2 v) const {
        float2 bb = *(const float2*)(bias + n0 + ni);
        v.x += bb.x; v.y += bb.y;
        *(float2*)(C + (size_t)(m0 + mi) * Eq + (n0 + ni)) = v;
    }
};

// ---------------------------------------------------------------------------
__global__ __launch_bounds__(256, 1) void k_qkv(const float* __restrict__ q,
                                                const float* __restrict__ W,
                                                const float* __restrict__ bias) {
    EpiQKV e{(int)blockIdx.y * 128, (int)blockIdx.x * 128, bias};
    mm_main<128>(q + (size_t)e.m0 * Eq, Eq, W + (size_t)e.n0 * Eq, Eq, Eq, e);
}

__global__ __launch_bounds__(256, 1) void k_qe(const float* __restrict__ er) {
    if (blockIdx.x + blockIdx.y < 7) return;   // band tiles only
    int bh = blockIdx.z;
    int m0 = blockIdx.y * 128, n0 = blockIdx.x * 128;
    EpiStore e{g_qe + (size_t)bh * Lq * Lq, m0, n0};
    mm_main<128>(g_q + (size_t)bh * Lq * Dh + (size_t)m0 * Dh, Dh,
                 er + (size_t)n0 * Dh, Dh, Dh, e);
}

// ---------------------------------------------------------------------------
// Fused attention, double-buffered K/V stages (2 x 64KB dynamic smem)
// fp16 x2: Q & P rounded, K & V split hi/lo.
// ---------------------------------------------------------------------------
__global__ __launch_bounds__(256, 1) void k_attn() {
    extern __shared__ char sm[];
    const uint32_t su = (uint32_t)__cvta_generic_to_shared(sm);
    // stage s: Kh = s*65536, Kl = +16384, Vh = +32768, Vl = +49152

    const int tid = threadIdx.x, lane = tid & 31, w = tid >> 5;
    const int m0 = blockIdx.x * 128, bh = blockIdx.y;
    const int rb = w * 16;

    const float* __restrict__ Qg = g_q + (size_t)bh * Lq * Dh + (size_t)m0 * Dh;
    const float* __restrict__ Kg = g_k + (size_t)bh * Lq * Dh;
    const float* __restrict__ Vg = g_v + (size_t)bh * Dh * Lq;   // (D, L)

    // ---- stage Q (rounded fp16) through stage0 K area, pull frags ----
    #pragma unroll
    for (int i = 0; i < 8; i++) {
        int qd = tid + i * 256; int r = qd >> 4, c = (qd & 15) * 4;
        float4 v = *(const float4*)(Qg + (size_t)r * Dh + c);
        uint32_t off = SWZ128((uint32_t)(r * 128 + c * 2));
        *(uint2*)(sm + off) = pack4_f16(v);
    }
    __syncthreads();
    uint32_t qh[4][4];
    {
        uint32_t arow = rb + (lane & 15);
        uint32_t ak   = (lane >> 4) * 8;
        #pragma unroll
        for (int kc = 0; kc < 4; kc++) {
            uint32_t off = SWZ128(arow * 128 + (kc * 16 + ak) * 2);
            ldsm4(qh[kc], su + off);
        }
    }
    __syncthreads();   // all warps done reading Q before stage0 refilled

    float4 ka[8], vv[8];
    auto loadK = [&](int n0) {
        #pragma unroll
        for (int i = 0; i < 8; i++) {
            int qd = tid + i * 256; int r = qd >> 4, c = (qd & 15) * 4;
            ka[i] = *(const float4*)(Kg + (size_t)(n0 + r) * Dh + c);
        }
    };
    auto storeK = [&](int s) {
        char* base = sm + s * 65536;
        #pragma unroll
        for (int i = 0; i < 8; i++) {
            int qd = tid + i * 256; int r = qd >> 4, c = (qd & 15) * 4;
            uint2 hi, lo; split_f16(ka[i], hi, lo);
            uint32_t off = SWZ128((uint32_t)(r * 128 + c * 2));
            *(uint2*)(base + off)         = hi;
            *(uint2*)(base + 16384 + off) = lo;
        }
    };
    auto loadV = [&](int n0) {
        #pragma unroll
        for (int i = 0; i < 8; i++) {
            int qd = tid + i * 256; int r = qd >> 5, c = (qd & 31) * 4;
            vv[i] = *(const float4*)(Vg + (size_t)r * Lq + n0 + c);
        }
    };
    auto storeV = [&](int s) {
        char* base = sm + s * 65536 + 32768;
        #pragma unroll
        for (int i = 0; i < 8; i++) {
            int qd = tid + i * 256; int r = qd >> 5, c = (qd & 31) * 4;
            uint2 hi, lo; split_f16(vv[i], hi, lo);
            uint32_t off = SWZ256((uint32_t)(r * 256 + c * 2));
            *(uint2*)(base + off)         = hi;
            *(uint2*)(base + 16384 + off) = lo;
        }
    };

    float o[8][4];
    #pragma unroll
    for (int f = 0; f < 8; f++) { o[f][0]=0.f; o[f][1]=0.f; o[f][2]=0.f; o[f][3]=0.f; }
    float mst0 = -3.4e38f, mst1 = -3.4e38f, sum0 = 0.f, sum1 = 0.f;

    const uint32_t brow = (lane & 7) + ((lane >> 4) & 1) * 8;
    const uint32_t bk8  = ((lane >> 3) & 1) * 8;
    const int l0 = m0 + rb + (lane >> 2), l1 = l0 + 8;
    const float L2E = 1.4426950408889634f;

    loadK(0); storeK(0);
    loadV(0); storeV(0);
    __syncthreads();

    for (int nb = 0; nb < 8; nb++) {
        const int n0  = nb * 128;
        const int cur = nb & 1;
        const uint32_t suK  = su + cur * 65536;
        const uint32_t suKl = suK + 16384;
        const uint32_t suV  = suK + 32768;
        const uint32_t suVl = suK + 49152;

        if (nb < 7) loadK(n0 + 128);

        // S = Q K^T (Q rounded, K split)
        float s[16][4];
        #pragma unroll
        for (int f = 0; f < 16; f++) { s[f][0]=0.f; s[f][1]=0.f; s[f][2]=0.f; s[f][3]=0.f; }
        #pragma unroll
        for (int n16 = 0; n16 < 8; n16++) {
            #pragma unroll
            for (int kc = 0; kc < 4; kc++) {
                uint32_t off = SWZ128((n16 * 16 + brow) * 128 + (kc * 16 + bk8) * 2);
                uint32_t kh4[4], kl4[4];
                ldsm4(kh4, suK + off); ldsm4(kl4, suKl + off);
                mma_f16(s[2*n16],   qh[kc], kh4[0], kh4[1]);
                mma_f16(s[2*n16],   qh[kc], kl4[0], kl4[1]);
                mma_f16(s[2*n16+1], qh[kc], kh4[2], kh4[3]);
                mma_f16(s[2*n16+1], qh[kc], kl4[2], kl4[3]);
            }
        }

        if (nb < 7) { storeK(cur ^ 1); loadV(n0 + 128); }

        // srel: s[l][m] += qe[l][1023 + m - l]  for m <= l
        if (n0 <= m0) {
            const float* q0 = g_qe + ((size_t)bh * Lq + l0) * Lq + (1023 - l0);
            const float* q1 = g_qe + ((size_t)bh * Lq + l1) * Lq + (1023 - l1);
            #pragma unroll
            for (int f = 0; f < 16; f++) {
                int m = n0 + f * 8 + (lane & 3) * 2;
                if (m < l0)       { s[f][0] += q0[m]; s[f][1] += q0[m + 1]; }
                else if (m == l0) { s[f][0] += q0[m]; }
                if (m < l1)       { s[f][2] += q1[m]; s[f][3] += q1[m + 1]; }
                else if (m == l1) { s[f][2] += q1[m]; }
            }
        }

        // online softmax (quad-local rows)
        float mx0 = -3.4e38f, mx1 = -3.4e38f;
        #pragma unroll
        for (int f = 0; f < 16; f++) {
            mx0 = fmaxf(mx0, fmaxf(s[f][0], s[f][1]));
            mx1 = fmaxf(mx1, fmaxf(s[f][2], s[f][3]));
        }
        mx0 = fmaxf(mx0, __shfl_xor_sync(0xffffffffu, mx0, 1));
        mx0 = fmaxf(mx0, __shfl_xor_sync(0xffffffffu, mx0, 2));
        mx1 = fmaxf(mx1, __shfl_xor_sync(0xffffffffu, mx1, 1));
        mx1 = fmaxf(mx1, __shfl_xor_sync(0xffffffffu, mx1, 2));
        float nm0 = fmaxf(mst0, mx0), nm1 = fmaxf(mst1, mx1);
        float sc0 = exp2f((mst0 - nm0) * L2E), sc1 = exp2f((mst1 - nm1) * L2E);
        mst0 = nm0; mst1 = nm1;
        sum0 *= sc0; sum1 *= sc1;
        #pragma unroll
        for (int f = 0; f < 8; f++) {
            o[f][0] *= sc0; o[f][1] *= sc0; o[f][2] *= sc1; o[f][3] *= sc1;
        }
        #pragma unroll
        for (int f = 0; f < 16; f++) {
            s[f][0] = exp2f((s[f][0] - nm0) * L2E);
            s[f][1] = exp2f((s[f][1] - nm0) * L2E);
            s[f][2] = exp2f((s[f][2] - nm1) * L2E);
            s[f][3] = exp2f((s[f][3] - nm1) * L2E);
            sum0 += s[f][0] + s[f][1];
            sum1 += s[f][2] + s[f][3];
        }

        if (nb < 7) storeV(cur ^ 1);

        // O += P V  (P rounded, V split)
        #pragma unroll
        for (int kk = 0; kk < 8; kk++) {
            uint32_t ahp[4];
            ahp[0] = packh(s[2*kk][0],   s[2*kk][1]);
            ahp[1] = packh(s[2*kk][2],   s[2*kk][3]);
            ahp[2] = packh(s[2*kk+1][0], s[2*kk+1][1]);
            ahp[3] = packh(s[2*kk+1][2], s[2*kk+1][3]);
            #pragma unroll
            for (int n16 = 0; n16 < 4; n16++) {
                uint32_t off = SWZ256((n16 * 16 + brow) * 256 + (kk * 16 + bk8) * 2);
                uint32_t vh4[4], vl4[4];
                ldsm4(vh4, suV + off); ldsm4(vl4, suVl + off);
                mma_f16(o[2*n16],   ahp, vh4[0], vh4[1]);
                mma_f16(o[2*n16],   ahp, vl4[0], vl4[1]);
                mma_f16(o[2*n16+1], ahp, vh4[2], vh4[3]);
                mma_f16(o[2*n16+1], ahp, vl4[2], vl4[3]);
            }
        }
        __syncthreads();
    }

    // finalize
    sum0 += __shfl_xor_sync(0xffffffffu, sum0, 1);
    sum0 += __shfl_xor_sync(0xffffffffu, sum0, 2);
    sum1 += __shfl_xor_sync(0xffffffffu, sum1, 1);
    sum1 += __shfl_xor_sync(0xffffffffu, sum1, 2);
    const float inv0 = 1.0f / sum0, inv1 = 1.0f / sum1;
    const int b = bh >> 4, h = bh & 15;
    #pragma unroll
    for (int f = 0; f < 8; f++) {
        int d = f * 8 + (lane & 3) * 2;
        float2 v0 = make_float2(o[f][0] * inv0, o[f][1] * inv0);
        float2 v1 = make_float2(o[f][2] * inv1, o[f][3] * inv1);
        *(float2*)(g_ctx + (size_t)l0 * (Bq * Eq) + b * Eq + h * Dh + d) = v0;
        *(float2*)(g_ctx + (size_t)l1 * (Bq * Eq) + b * Eq + h * Dh + d) = v1;
    }
}

__global__ __launch_bounds__(256, 1) void k_outproj(const float* __restrict__ W,
                                                    const float* __restrict__ bias,
                                                    float* __restrict__ out) {
    int m0 = blockIdx.y * 128, n0 = blockIdx.x * 128;
    EpiBias e{out, bias, m0, n0};
    mm_main<128>(g_ctx + (size_t)m0 * Eq, Eq, W + (size_t)n0 * Eq, Eq, Eq, e);
}

// ---------------------------------------------------------------------------
extern "C" void kernel_launch(void* const* d_in, const int* in_sizes, int n_in,
                              void* d_out, int out_size)
{
    (void)in_sizes; (void)n_in; (void)out_size;
    const float* query  = (const float*)d_in[0];
    const float* relpos = (const float*)d_in[1];
    const float* w_in   = (const float*)d_in[2];
    const float* b_in   = (const float*)d_in[3];
    const float* w_out  = (const float*)d_in[4];
    const float* b_out  = (const float*)d_in[5];
    float* out = (float*)d_out;

    const int SMG = 2 * (8192 + 2 * 128 * 64);   // 49152 for NT=128
    cudaFuncSetAttribute(k_qkv,     cudaFuncAttributeMaxDynamicSharedMemorySize, SMG);
    cudaFuncSetAttribute(k_qe,      cudaFuncAttributeMaxDynamicSharedMemorySize, SMG);
    cudaFuncSetAttribute(k_outproj, cudaFuncAttributeMaxDynamicSharedMemorySize, SMG);
    cudaFuncSetAttribute(k_attn,    cudaFuncAttributeMaxDynamicSharedMemorySize, 131072);

    k_qkv    <<<dim3(24, 32),   256, SMG>>>(query, w_in, b_in);
    k_qe     <<<dim3(8, 8, 64), 256, SMG>>>(relpos);
    k_attn   <<<dim3(8, 64),    256, 131072>>>();
    k_outproj<<<dim3(8, 32),    256, SMG>>>(w_out, b_out, out);
}

// round 11
// speedup vs baseline: 1.3095x; 1.1529x over previous
#include <cuda_runtime.h>
#include <cuda_fp16.h>
#include <stdint.h>

#define NH 16
#define Dh 64
#define Lq 1024
#define Bq 4
#define Eq 1024
#define BH 64

// ---- scratch (device globals) ----
__device__ __half g_query_h[4096*1024];      // query rounded fp16 (L*B, E)
__device__ __half g_win_h[3*1024*1024];      // W_in split
__device__ __half g_win_l[3*1024*1024];
__device__ __half g_wout_h[1024*1024];       // W_out split
__device__ __half g_wout_l[1024*1024];
__device__ __half g_er_h[1024*64];           // relpos split
__device__ __half g_er_l[1024*64];
__device__ __half g_qh[BH*Lq*Dh];            // q rounded, pre-scaled 1/8 (BH,L,D)
__device__ __half g_kh[BH*Lq*Dh];            // k split (BH,L,D)
__device__ __half g_kl[BH*Lq*Dh];
__device__ __half g_vh[BH*Lq*Dh];            // v split TRANSPOSED (BH,D,L)
__device__ __half g_vl[BH*Lq*Dh];
__device__ float  g_qe[(size_t)BH*Lq*Lq];    // relpos logits fp32 (band only)
__device__ __half g_ctx_h[Lq*Bq*Eq];         // ctx rounded fp16 (L,B,E)

#define SWZ64(x)  ((x) ^ (((x) >> 3) & 0x30))
#define SWZ128(x) ((x) ^ (((x) >> 3) & 0x70))
#define SWZ256(x) ((x) ^ (((x) >> 4) & 0x70))

__device__ __forceinline__ void ldsm4(uint32_t (&r)[4], uint32_t addr) {
    asm volatile("ldmatrix.sync.aligned.m8n8.x4.shared.b16 {%0,%1,%2,%3}, [%4];"
                 : "=r"(r[0]), "=r"(r[1]), "=r"(r[2]), "=r"(r[3]) : "r"(addr));
}
__device__ __forceinline__ void mma_f16(float (&d)[4], const uint32_t (&a)[4],
                                        uint32_t b0, uint32_t b1) {
    asm volatile("mma.sync.aligned.m16n8k16.row.col.f32.f16.f16.f32 "
                 "{%0,%1,%2,%3}, {%4,%5,%6,%7}, {%8,%9}, {%0,%1,%2,%3};"
                 : "+f"(d[0]), "+f"(d[1]), "+f"(d[2]), "+f"(d[3])
                 : "r"(a[0]), "r"(a[1]), "r"(a[2]), "r"(a[3]), "r"(b0), "r"(b1));
}
__device__ __forceinline__ void cp16(uint32_t smem, const void* g) {
    asm volatile("cp.async.cg.shared.global [%0], [%1], 16;"
                 :: "r"(smem), "l"(g) : "memory");
}
#define CP_COMMIT() asm volatile("cp.async.commit_group;" ::: "memory")
#define CP_WAIT(N)  asm volatile("cp.async.wait_group %0;" :: "n"(N) : "memory")

__device__ __forceinline__ uint32_t packh(float a, float b) {
    __half2 t = __floats2half2_rn(a, b);
    return *(uint32_t*)&t;
}

// ---------------------------------------------------------------------------
// Prep kernels: fp32 -> fp16 (round / split)
// ---------------------------------------------------------------------------
__global__ __launch_bounds__(256) void k_round(const float* __restrict__ in,
                                               __half* __restrict__ oh, int n2) {
    int i = blockIdx.x * 256 + threadIdx.x;
    if (i < n2) {
        float2 v = ((const float2*)in)[i];
        ((__half2*)oh)[i] = __floats2half2_rn(v.x, v.y);
    }
}
__global__ __launch_bounds__(256) void k_split(const float* __restrict__ in,
                                               __half* __restrict__ oh,
                                               __half* __restrict__ ol, int n2) {
    int i = blockIdx.x * 256 + threadIdx.x;
    if (i < n2) {
        float2 v = ((const float2*)in)[i];
        __half2 hi = __floats2half2_rn(v.x, v.y);
        __half2 lo = __floats2half2_rn(v.x - __low2float(hi), v.y - __high2float(hi));
        ((__half2*)oh)[i] = hi;
        ((__half2*)ol)[i] = lo;
    }
}

// ---------------------------------------------------------------------------
// GEMM: C(128 x 128) = A(128 x K) * B(128 x K)^T, all-fp16 operands in gmem.
// A rounded fp16; B as hi/lo split (x2 MMA). cp.async 3-stage pipeline.
// 256 thr, warp grid 2x4. Dynamic smem 3 x 24KB = 72KB.
// ---------------------------------------------------------------------------
template<class Epi>
__device__ __forceinline__ void mm_f16(const __half* __restrict__ A, int lda,
                                       const __half* __restrict__ Bh,
                                       const __half* __restrict__ Bl, int ldb,
                                       int K, Epi epi)
{
    constexpr int ASZ = 8192;          // 128 x 32 fp16
    constexpr int BSZ = 8192;          // 128 x 32 fp16
    constexpr int STG = ASZ + 2 * BSZ; // 24KB

    extern __shared__ char dsm[];
    const uint32_t su = (uint32_t)__cvta_generic_to_shared(dsm);

    const int tid  = threadIdx.x;
    const int lane = tid & 31, w = tid >> 5;
    const int m_base = (w & 1) * 64;
    const int n_base = (w >> 1) * 32;

    float acc[4][4][4];
    #pragma unroll
    for (int i = 0; i < 4; i++)
        #pragma unroll
        for (int j = 0; j < 4; j++)
            #pragma unroll
            for (int q = 0; q < 4; q++) acc[i][j][q] = 0.f;

    const uint32_t a_row = lane & 15;
    const uint32_t a_k8  = (lane >> 4) * 8;
    const uint32_t b_row = (lane & 7) + ((lane >> 4) & 1) * 8;
    const uint32_t b_k8  = ((lane >> 3) & 1) * 8;

    auto issue = [&](int s, int kb) {
        const uint32_t base = su + s * STG;
        #pragma unroll
        for (int i = 0; i < 2; i++) {
            int id = tid + i * 256; int r = id >> 2, c = id & 3;
            uint32_t off = SWZ64((uint32_t)(r * 64 + c * 16));
            cp16(base + off, A + (size_t)r * lda + kb + c * 8);
        }
        #pragma unroll
        for (int i = 0; i < 2; i++) {
            int id = tid + i * 256; int r = id >> 2, c = id & 3;
            uint32_t off = SWZ64((uint32_t)(r * 64 + c * 16));
            const size_t gix = (size_t)r * ldb + kb + c * 8;
            cp16(base + ASZ + off,       Bh + gix);
            cp16(base + ASZ + BSZ + off, Bl + gix);
        }
        CP_COMMIT();
    };
    auto domma = [&](int s) {
        const uint32_t sbA  = su + s * STG;
        const uint32_t sbB  = sbA + ASZ;
        const uint32_t sbBl = sbB + BSZ;
        #pragma unroll
        for (int kc = 0; kc < 2; kc++) {
            uint32_t ah[4][4];
            #pragma unroll
            for (int mt = 0; mt < 4; mt++) {
                uint32_t off = SWZ64((uint32_t)((m_base + mt * 16 + a_row) * 64
                                                + (kc * 16 + a_k8) * 2));
                ldsm4(ah[mt], sbA + off);
            }
            uint32_t bh[2][4], bl[2][4];
            #pragma unroll
            for (int nb = 0; nb < 2; nb++) {
                uint32_t off = SWZ64((uint32_t)((n_base + nb * 16 + b_row) * 64
                                                + (kc * 16 + b_k8) * 2));
                ldsm4(bh[nb], sbB  + off);
                ldsm4(bl[nb], sbBl + off);
            }
            #pragma unroll
            for (int mt = 0; mt < 4; mt++)
                #pragma unroll
                for (int nt = 0; nt < 4; nt++) {
                    uint32_t b0h = bh[nt >> 1][(nt & 1) * 2];
                    uint32_t b1h = bh[nt >> 1][(nt & 1) * 2 + 1];
                    uint32_t b0l = bl[nt >> 1][(nt & 1) * 2];
                    uint32_t b1l = bl[nt >> 1][(nt & 1) * 2 + 1];
                    mma_f16(acc[mt][nt], ah[mt], b0h, b1h);
                    mma_f16(acc[mt][nt], ah[mt], b0l, b1l);
                }
        }
    };

    const int nk = K >> 5;
    issue(0, 0);
    issue(1, 32);
    for (int i = 0; i < nk; i++) {
        if (i + 1 < nk) { CP_WAIT(1); } else { CP_WAIT(0); }
        __syncthreads();
        if (i + 2 < nk) issue((i + 2) % 3, (i + 2) * 32);
        domma(i % 3);
    }

    #pragma unroll
    for (int mt = 0; mt < 4; mt++)
        #pragma unroll
        for (int nt = 0; nt < 4; nt++) {
            int m = m_base + mt * 16 + (lane >> 2);
            int n = n_base + nt * 8 + (lane & 3) * 2;
            epi(m,     n, make_float2(acc[mt][nt][0], acc[mt][nt][1]));
            epi(m + 8, n, make_float2(acc[mt][nt][2], acc[mt][nt][3]));
        }
}

// ---------------------------------------------------------------------------
// Epilogues
// ---------------------------------------------------------------------------
struct EpiQKV {
    int m0, n0; const float* bias;
    __device__ __forceinline__ void operator()(int mi, int ni, float2 v) const {
        int m = m0 + mi, n = n0 + ni;
        float2 bb = *(const float2*)(bias + n);
        v.x += bb.x; v.y += bb.y;
        int l = m >> 2, b = m & 3;
        int sec = n >> 10, e = n & 1023, h = e >> 6, d = e & 63;
        if (sec == 0) {
            v.x *= 0.125f; v.y *= 0.125f;
            *(__half2*)(g_qh + (((b * NH + h) * Lq + l) * Dh + d)) =
                __floats2half2_rn(v.x, v.y);
        } else if (sec == 1) {
            __half2 hi = __floats2half2_rn(v.x, v.y);
            __half2 lo = __floats2half2_rn(v.x - __low2float(hi),
                                           v.y - __high2float(hi));
            size_t ix = (((b * NH + h) * Lq + l) * Dh + d);
            *(__half2*)(g_kh + ix) = hi;
            *(__half2*)(g_kl + ix) = lo;
        } else {
            __half2 hi = __floats2half2_rn(v.x, v.y);
            __half2 lo = __floats2half2_rn(v.x - __low2float(hi),
                                           v.y - __high2float(hi));
            size_t ix = ((size_t)(b * NH + h) * Dh + d) * Lq + l;
            g_vh[ix]      = __low2half(hi);
            g_vh[ix + Lq] = __high2half(hi);
            g_vl[ix]      = __low2half(lo);
            g_vl[ix + Lq] = __high2half(lo);
        }
    }
};
struct EpiStore {
    float* C; int m0, n0;
    __device__ __forceinline__ void operator()(int mi, int ni, float2 v) const {
        *(float2*)(C + (size_t)(m0 + mi) * Lq + (n0 + ni)) = v;
    }
};
struct EpiBias {
    float* C; const float* bias; int m0, n0;
    __device__ __forceinline__ void operator()(int mi, int ni, float2 v) const {
        float2 bb = *(const float2*)(bias + n0 + ni);
        v.x += bb.x; v.y += bb.y;
        *(float2*)(C + (size_t)(m0 + mi) * Eq + (n0 + ni)) = v;
    }
};

// ---------------------------------------------------------------------------
__global__ __launch_bounds__(256, 2) void k_qkv(const float* __restrict__ bias) {
    EpiQKV e{(int)blockIdx.y * 128, (int)blockIdx.x * 128, bias};
    mm_f16(g_query_h + (size_t)e.m0 * Eq, Eq,
           g_win_h + (size_t)e.n0 * Eq, g_win_l + (size_t)e.n0 * Eq, Eq, Eq, e);
}

__global__ __launch_bounds__(256, 2) void k_qe() {
    if (blockIdx.x + blockIdx.y < 7) return;   // band tiles only
    int bh = blockIdx.z;
    int m0 = blockIdx.y * 128, n0 = blockIdx.x * 128;
    EpiStore e{g_qe + (size_t)bh * Lq * Lq, m0, n0};
    mm_f16(g_qh + (size_t)bh * Lq * Dh + (size_t)m0 * Dh, Dh,
           g_er_h + (size_t)n0 * Dh, g_er_l + (size_t)n0 * Dh, Dh, Dh, e);
}

__global__ __launch_bounds__(256, 2) void k_outproj(const float* __restrict__ bias,
                                                    float* __restrict__ out) {
    int m0 = blockIdx.y * 128, n0 = blockIdx.x * 128;
    EpiBias e{out, bias, m0, n0};
    mm_f16(g_ctx_h + (size_t)m0 * Eq, Eq,
           g_wout_h + (size_t)n0 * Eq, g_wout_l + (size_t)n0 * Eq, Eq, Eq, e);
}

// ---------------------------------------------------------------------------
// Fused attention, cp.async double-buffered K/V (2 x 64KB dynamic smem).
// Q & P rounded fp16; K & V pre-split hi/lo in gmem.
// ---------------------------------------------------------------------------
__global__ __launch_bounds__(256, 1) void k_attn() {
    extern __shared__ char sm[];
    const uint32_t su = (uint32_t)__cvta_generic_to_shared(sm);
    // stage s: Kh = s*65536, Kl = +16384, Vh = +32768, Vl = +49152

    const int tid = threadIdx.x, lane = tid & 31, w = tid >> 5;
    const int m0 = blockIdx.x * 128, bh = blockIdx.y;
    const int rb = w * 16;

    const __half* __restrict__ Qg = g_qh + (size_t)bh * Lq * Dh + (size_t)m0 * Dh;

    // ---- stage Q via cp.async into stage0 K area, pull frags ----
    #pragma unroll
    for (int i = 0; i < 4; i++) {
        int id = tid + i * 256; int r = id >> 3, c = id & 7;
        cp16(su + SWZ128((uint32_t)(r * 128 + c * 16)), Qg + (size_t)r * Dh + c * 8);
    }
    CP_COMMIT(); CP_WAIT(0);
    __syncthreads();
    uint32_t qh[4][4];
    {
        uint32_t arow = rb + (lane & 15);
        uint32_t ak   = (lane >> 4) * 8;
        #pragma unroll
        for (int kc = 0; kc < 4; kc++) {
            uint32_t off = SWZ128(arow * 128 + (kc * 16 + ak) * 2);
            ldsm4(qh[kc], su + off);
        }
    }
    __syncthreads();   // Q reads done before stage0 is refilled

    auto issueKV = [&](int nb) {
        const int n0 = nb * 128, s = nb & 1;
        const uint32_t base = su + s * 65536;
        #pragma unroll
        for (int i = 0; i < 4; i++) {
            int id = tid + i * 256; int r = id >> 3, c = id & 7;
            uint32_t off = SWZ128((uint32_t)(r * 128 + c * 16));
            const size_t gix = (size_t)bh * Lq * Dh + (size_t)(n0 + r) * Dh + c * 8;
            cp16(base + off,         g_kh + gix);
            cp16(base + 16384 + off, g_kl + gix);
        }
        #pragma unroll
        for (int i = 0; i < 4; i++) {
            int id = tid + i * 256; int r = id >> 4, c = id & 15;
            uint32_t off = SWZ256((uint32_t)(r * 256 + c * 16));
            const size_t gix = ((size_t)bh * Dh + r) * Lq + n0 + c * 8;
            cp16(base + 32768 + off, g_vh + gix);
            cp16(base + 49152 + off, g_vl + gix);
        }
        CP_COMMIT();
    };

    float o[8][4];
    #pragma unroll
    for (int f = 0; f < 8; f++) { o[f][0]=0.f; o[f][1]=0.f; o[f][2]=0.f; o[f][3]=0.f; }
    float mst0 = -3.4e38f, mst1 = -3.4e38f, sum0 = 0.f, sum1 = 0.f;

    const uint32_t brow = (lane & 7) + ((lane >> 4) & 1) * 8;
    const uint32_t bk8  = ((lane >> 3) & 1) * 8;
    const int l0 = m0 + rb + (lane >> 2), l1 = l0 + 8;
    const float L2E = 1.4426950408889634f;

    issueKV(0);

    for (int nb = 0; nb < 8; nb++) {
        const int n0  = nb * 128;
        const int cur = nb & 1;
        const uint32_t suK  = su + cur * 65536;
        const uint32_t suKl = suK + 16384;
        const uint32_t suV  = suK + 32768;
        const uint32_t suVl = suK + 49152;

        CP_WAIT(0);
        __syncthreads();
        if (nb < 7) issueKV(nb + 1);   // copies overlap this block's compute

        // S = Q K^T (Q rounded, K split)
        float s[16][4];
        #pragma unroll
        for (int f = 0; f < 16; f++) { s[f][0]=0.f; s[f][1]=0.f; s[f][2]=0.f; s[f][3]=0.f; }
        #pragma unroll
        for (int n16 = 0; n16 < 8; n16++) {
            #pragma unroll
            for (int kc = 0; kc < 4; kc++) {
                uint32_t off = SWZ128((n16 * 16 + brow) * 128 + (kc * 16 + bk8) * 2);
                uint32_t kh4[4], kl4[4];
                ldsm4(kh4, suK + off); ldsm4(kl4, suKl + off);
                mma_f16(s[2*n16],   qh[kc], kh4[0], kh4[1]);
                mma_f16(s[2*n16],   qh[kc], kl4[0], kl4[1]);
                mma_f16(s[2*n16+1], qh[kc], kh4[2], kh4[3]);
                mma_f16(s[2*n16+1], qh[kc], kl4[2], kl4[3]);
            }
        }

        // srel: s[l][m] += qe[l][1023 + m - l]  for m <= l
        if (n0 <= m0) {
            const float* q0 = g_qe + ((size_t)bh * Lq + l0) * Lq + (1023 - l0);
            const float* q1 = g_qe + ((size_t)bh * Lq + l1) * Lq + (1023 - l1);
            #pragma unroll
            for (int f = 0; f < 16; f++) {
                int m = n0 + f * 8 + (lane & 3) * 2;
                if (m < l0)       { s[f][0] += q0[m]; s[f][1] += q0[m + 1]; }
                else if (m == l0) { s[f][0] += q0[m]; }
                if (m < l1)       { s[f][2] += q1[m]; s[f][3] += q1[m + 1]; }
                else if (m == l1) { s[f][2] += q1[m]; }
            }
        }

        // online softmax (quad-local rows)
        float mx0 = -3.4e38f, mx1 = -3.4e38f;
        #pragma unroll
        for (int f = 0; f < 16; f++) {
            mx0 = fmaxf(mx0, fmaxf(s[f][0], s[f][1]));
            mx1 = fmaxf(mx1, fmaxf(s[f][2], s[f][3]));
        }
        mx0 = fmaxf(mx0, __shfl_xor_sync(0xffffffffu, mx0, 1));
        mx0 = fmaxf(mx0, __shfl_xor_sync(0xffffffffu, mx0, 2));
        mx1 = fmaxf(mx1, __shfl_xor_sync(0xffffffffu, mx1, 1));
        mx1 = fmaxf(mx1, __shfl_xor_sync(0xffffffffu, mx1, 2));
        float nm0 = fmaxf(mst0, mx0), nm1 = fmaxf(mst1, mx1);
        float sc0 = exp2f((mst0 - nm0) * L2E), sc1 = exp2f((mst1 - nm1) * L2E);
        mst0 = nm0; mst1 = nm1;
        sum0 *= sc0; sum1 *= sc1;
        #pragma unroll
        for (int f = 0; f < 8; f++) {
            o[f][0] *= sc0; o[f][1] *= sc0; o[f][2] *= sc1; o[f][3] *= sc1;
        }
        #pragma unroll
        for (int f = 0; f < 16; f++) {
            s[f][0] = exp2f((s[f][0] - nm0) * L2E);
            s[f][1] = exp2f((s[f][1] - nm0) * L2E);
            s[f][2] = exp2f((s[f][2] - nm1) * L2E);
            s[f][3] = exp2f((s[f][3] - nm1) * L2E);
            sum0 += s[f][0] + s[f][1];
            sum1 += s[f][2] + s[f][3];
        }

        // O += P V  (P rounded, V split)
        #pragma unroll
        for (int kk = 0; kk < 8; kk++) {
            uint32_t ahp[4];
            ahp[0] = packh(s[2*kk][0],   s[2*kk][1]);
            ahp[1] = packh(s[2*kk][2],   s[2*kk][3]);
            ahp[2] = packh(s[2*kk+1][0], s[2*kk+1][1]);
            ahp[3] = packh(s[2*kk+1][2], s[2*kk+1][3]);
            #pragma unroll
            for (int n16 = 0; n16 < 4; n16++) {
                uint32_t off = SWZ256((n16 * 16 + brow) * 256 + (kk * 16 + bk8) * 2);
                uint32_t vh4[4], vl4[4];
                ldsm4(vh4, suV + off); ldsm4(vl4, suVl + off);
                mma_f16(o[2*n16],   ahp, vh4[0], vh4[1]);
                mma_f16(o[2*n16],   ahp, vl4[0], vl4[1]);
                mma_f16(o[2*n16+1], ahp, vh4[2], vh4[3]);
                mma_f16(o[2*n16+1], ahp, vl4[2], vl4[3]);
            }
        }
    }

    // finalize: write ctx as rounded fp16
    sum0 += __shfl_xor_sync(0xffffffffu, sum0, 1);
    sum0 += __shfl_xor_sync(0xffffffffu, sum0, 2);
    sum1 += __shfl_xor_sync(0xffffffffu, sum1, 1);
    sum1 += __shfl_xor_sync(0xffffffffu, sum1, 2);
    const float inv0 = 1.0f / sum0, inv1 = 1.0f / sum1;
    const int b = bh >> 4, h = bh & 15;
    #pragma unroll
    for (int f = 0; f < 8; f++) {
        int d = f * 8 + (lane & 3) * 2;
        *(__half2*)(g_ctx_h + (size_t)l0 * (Bq * Eq) + b * Eq + h * Dh + d) =
            __floats2half2_rn(o[f][0] * inv0, o[f][1] * inv0);
        *(__half2*)(g_ctx_h + (size_t)l1 * (Bq * Eq) + b * Eq + h * Dh + d) =
            __floats2half2_rn(o[f][2] * inv1, o[f][3] * inv1);
    }
}

// ---------------------------------------------------------------------------
extern "C" void kernel_launch(void* const* d_in, const int* in_sizes, int n_in,
                              void* d_out, int out_size)
{
    (void)in_sizes; (void)n_in; (void)out_size;
    const float* query  = (const float*)d_in[0];
    const float* relpos = (const float*)d_in[1];
    const float* w_in   = (const float*)d_in[2];
    const float* b_in   = (const float*)d_in[3];
    const float* w_out  = (const float*)d_in[4];
    const float* b_out  = (const float*)d_in[5];
    float* out = (float*)d_out;

    const int SMG = 3 * (8192 + 2 * 8192);   // 73728
    cudaFuncSetAttribute(k_qkv,     cudaFuncAttributeMaxDynamicSharedMemorySize, SMG);
    cudaFuncSetAttribute(k_qe,      cudaFuncAttributeMaxDynamicSharedMemorySize, SMG);
    cudaFuncSetAttribute(k_outproj, cudaFuncAttributeMaxDynamicSharedMemorySize, SMG);
    cudaFuncSetAttribute(k_attn,    cudaFuncAttributeMaxDynamicSharedMemorySize, 131072);

    __half *p_query, *p_win_h, *p_win_l, *p_wout_h, *p_wout_l, *p_er_h, *p_er_l;
    cudaGetSymbolAddress((void**)&p_query,  g_query_h);
    cudaGetSymbolAddress((void**)&p_win_h,  g_win_h);
    cudaGetSymbolAddress((void**)&p_win_l,  g_win_l);
    cudaGetSymbolAddress((void**)&p_wout_h, g_wout_h);
    cudaGetSymbolAddress((void**)&p_wout_l, g_wout_l);
    cudaGetSymbolAddress((void**)&p_er_h,   g_er_h);
    cudaGetSymbolAddress((void**)&p_er_l,   g_er_l);

    k_round<<<(4096*1024/2 + 255)/256, 256>>>(query, p_query, 4096*1024/2);
    k_split<<<(3*1024*1024/2 + 255)/256, 256>>>(w_in, p_win_h, p_win_l, 3*1024*1024/2);
    k_split<<<(1024*1024/2 + 255)/256, 256>>>(w_out, p_wout_h, p_wout_l, 1024*1024/2);
    k_split<<<(1024*64/2 + 255)/256, 256>>>(relpos, p_er_h, p_er_l, 1024*64/2);

    k_qkv    <<<dim3(24, 32),   256, SMG>>>(b_in);
    k_qe     <<<dim3(8, 8, 64), 256, SMG>>>();
    k_attn   <<<dim3(8, 64),    256, 131072>>>();
    k_outproj<<<dim3(8, 32),    256, SMG>>>(b_out, out);
}